// round 10
// baseline (speedup 1.0000x reference)
#include <cuda_runtime.h>

#define T_FRAMES 2048
#define D_HID    1024
#define V_VOC    28
#define ROWS     2
#define NBLK_A   (T_FRAMES / ROWS)      // 1024
#define CHUNK    16
#define NCHUNK   (T_FRAMES / CHUNK)     // 128

// ---------------------------------------------------------------------------
// Device scratch
// ---------------------------------------------------------------------------
__device__ float g_U[T_FRAMES * V_VOC];   // 0.5*(Uo . x[t-1]); row 0 rewritten by kMeta
__device__ float g_CO[V_VOC];             // 0.5*(Co @ colsum x)  (atomic-accumulated)
__device__ float g_partMn[V_VOC * NBLK_A];
__device__ float g_partMx[V_VOC * NBLK_A];
__device__ int   g_m;                     // number of active outputs
__device__ int   g_useSerial;
__device__ int   g_halo;                  // 8 or 16
__device__ int   g_actV[32];              // rank -> active v (zero padded)
__device__ float g_B28[32];               // per-v folded bias
__device__ float g_W28[32 * V_VOC];       // per-v 0.25*Wo[v, act[j]] (zero padded)

// ---------------------------------------------------------------------------
// Kernel A: g_U[t+1][v] = 0.5*(Uo[v] . x[t]) for 2 t-rows per block, fused
// with the partial CO dot (Co[v] . block-xsum -> atomicAdd) and min/max
// partials. 1024 blocks x 128 threads -> ~27 warps/SM; Uo/Co L1-resident.
// ---------------------------------------------------------------------------
__global__ void __launch_bounds__(128) kA_computeU(const float* __restrict__ x,
                                                   const float* __restrict__ Uo,
                                                   const float* __restrict__ Co) {
    __shared__ float xs[ROWS][D_HID];              // 8 KB
    const int t0 = blockIdx.x * ROWS;

    const float4* xv = reinterpret_cast<const float4*>(x + (size_t)t0 * D_HID);
    float4* sv = reinterpret_cast<float4*>(&xs[0][0]);
    #pragma unroll
    for (int i = 0; i < ROWS * D_HID / 4 / 128; i++)
        sv[threadIdx.x + 128 * i] = xv[threadIdx.x + 128 * i];
    __syncthreads();

    const int warp = threadIdx.x >> 5;
    const int lane = threadIdx.x & 31;

    float acc0[7], acc1[7], accC[7];
    #pragma unroll
    for (int vi = 0; vi < 7; vi++) { acc0[vi] = 0.f; acc1[vi] = 0.f; accC[vi] = 0.f; }

    #pragma unroll
    for (int j = 0; j < 8; j++) {
        const int dd = j * 128 + lane * 4;
        const float4 xr0 = *reinterpret_cast<const float4*>(&xs[0][dd]);
        const float4 xr1 = *reinterpret_cast<const float4*>(&xs[1][dd]);
        float4 xsum;
        xsum.x = xr0.x + xr1.x; xsum.y = xr0.y + xr1.y;
        xsum.z = xr0.z + xr1.z; xsum.w = xr0.w + xr1.w;
        #pragma unroll
        for (int vi = 0; vi < 7; vi++) {
            const int v = warp * 7 + vi;
            const float4 u4 = __ldg(reinterpret_cast<const float4*>(&Uo[v * D_HID + dd]));
            const float4 c4 = __ldg(reinterpret_cast<const float4*>(&Co[v * D_HID + dd]));
            float t0a = fmaf(u4.x, xr0.x, acc0[vi]);
            t0a = fmaf(u4.y, xr0.y, t0a);
            t0a = fmaf(u4.z, xr0.z, t0a);
            acc0[vi] = fmaf(u4.w, xr0.w, t0a);
            float t1a = fmaf(u4.x, xr1.x, acc1[vi]);
            t1a = fmaf(u4.y, xr1.y, t1a);
            t1a = fmaf(u4.z, xr1.z, t1a);
            acc1[vi] = fmaf(u4.w, xr1.w, t1a);
            float tc = fmaf(c4.x, xsum.x, accC[vi]);
            tc = fmaf(c4.y, xsum.y, tc);
            tc = fmaf(c4.z, xsum.z, tc);
            accC[vi] = fmaf(c4.w, xsum.w, tc);
        }
    }

    #pragma unroll
    for (int vi = 0; vi < 7; vi++) {
        const int v = warp * 7 + vi;
        float s0 = acc0[vi], s1 = acc1[vi], sc = accC[vi];
        #pragma unroll
        for (int o = 16; o; o >>= 1) {
            s0 += __shfl_xor_sync(0xFFFFFFFFu, s0, o);
            s1 += __shfl_xor_sync(0xFFFFFFFFu, s1, o);
            sc += __shfl_xor_sync(0xFFFFFFFFu, sc, o);
        }
        if (lane == 0) {
            const float uh0 = 0.5f * s0;           // -> t0+1 (always < T)
            g_U[(t0 + 1) * V_VOC + v] = uh0;
            float mn = uh0, mx = uh0;
            const int t2 = t0 + 2;
            if (t2 < T_FRAMES) {
                const float uh1 = 0.5f * s1;
                g_U[t2 * V_VOC + v] = uh1;
                mn = fminf(mn, uh1);
                mx = fmaxf(mx, uh1);
            }
            g_partMn[v * NBLK_A + blockIdx.x] = mn;
            g_partMx[v * NBLK_A + blockIdx.x] = mx;
            atomicAdd(&g_CO[v], 0.5f * sc);
        }
    }
}

// ---------------------------------------------------------------------------
// Kernel Meta: min/max reduce + classify + unified tables. 28 warps.
// ---------------------------------------------------------------------------
__global__ void __launch_bounds__(896) kMeta(const float* __restrict__ Wo) {
    const int warp = threadIdx.x >> 5;
    const int lane = threadIdx.x & 31;

    {   // per-v min/max reduce over 1024 block partials (include t=0 value 0)
        float mn = 0.f, mx = 0.f;
        #pragma unroll
        for (int i = 0; i < NBLK_A / 32; i++) {
            mn = fminf(mn, g_partMn[warp * NBLK_A + lane + 32 * i]);
            mx = fmaxf(mx, g_partMx[warp * NBLK_A + lane + 32 * i]);
        }
        #pragma unroll
        for (int o = 16; o; o >>= 1) {
            mn = fminf(mn, __shfl_xor_sync(0xFFFFFFFFu, mn, o));
            mx = fmaxf(mx, __shfl_xor_sync(0xFFFFFFFFu, mx, o));
        }
        if (lane == 0) { g_partMn[warp * NBLK_A] = mn; g_partMx[warp * NBLK_A] = mx; }
    }
    __syncthreads();
    if (warp != 0) return;

    // warp 0: classification + tables. All shuffles uniform.
    const bool valid = lane < V_VOC;
    const int vIdx = valid ? lane : 0;

    float w[V_VOC];
    float rowNeg = 0.f, rowPos = 0.f;
    #pragma unroll
    for (int k = 0; k < V_VOC; k++) {
        w[k] = Wo[vIdx * V_VOC + k];
        rowNeg += fminf(w[k], 0.f);
        rowPos += fmaxf(w[k], 0.f);
    }
    const float coh  = g_CO[vIdx];
    const float sMin = coh + g_partMn[vIdx * NBLK_A] + 0.5f * rowNeg;
    const float sMax = coh + g_partMx[vIdx * NBLK_A] + 0.5f * rowPos;

    int cls = 2;
    if (sMin > 7.f)  cls = 1;
    if (sMax < -7.f) cls = 0;
    if (!valid)      cls = 0;

    const unsigned amask = __ballot_sync(0xFFFFFFFFu, cls == 2) & 0x0FFFFFFFu;
    const int m = __popc(amask);
    if (lane == 0) g_m = m;

    int clsA[V_VOC];
    #pragma unroll
    for (int k = 0; k < V_VOC; k++)
        clsA[k] = __shfl_sync(0xFFFFFFFFu, cls, k);

    float s1 = 0.f;
    #pragma unroll
    for (int k = 0; k < V_VOC; k++)
        if (clsA[k] == 1) s1 += w[k];

    int act[V_VOC];
    int cnt = 0;
    #pragma unroll
    for (int k = 0; k < V_VOC; k++)
        if ((amask >> k) & 1u) act[cnt++] = k;

    // unified per-v tables: same folded form for active AND saturated rows
    float sa = 0.f, qrow = 0.f;
    #pragma unroll
    for (int j = 0; j < V_VOC; j++) {
        float wj = 0.f;
        if (j < m) wj = w[act[j]];
        g_W28[lane * V_VOC + j] = 0.25f * wj;
        sa += wj;
        qrow += 0.25f * fabsf(wj);
    }
    g_B28[lane] = coh + 0.5f * s1 + 0.25f * sa;
    g_actV[lane] = (lane < m) ? act[lane] : 0;

    if (cls != 2) qrow = 0.f;          // contraction over the active subsystem only
    #pragma unroll
    for (int o = 16; o; o >>= 1)
        qrow = fmaxf(qrow, __shfl_xor_sync(0xFFFFFFFFu, qrow, o));
    if (lane == 0) {
        g_useSerial = (m > 16 || qrow > 0.40f) ? 1 : 0;
        const float q = fmaxf(qrow, 1e-4f);
        g_halo = (9.f * __logf(q) < -16.2f) ? 8 : 16;
    }

    // t=0 exactness under folded-bias form: Uh0 = -0.5*s1
    if (valid) g_U[lane] = -0.5f * s1;
}

// ---------------------------------------------------------------------------
// One unified recurrence step (indexed shuffles from the active lanes)
// ---------------------------------------------------------------------------
template <int M, int NACC>
__device__ __forceinline__ float stepFn(const float* __restrict__ w,
                                        const int* __restrict__ src,
                                        float th, float bias) {
    float thc[M];
    #pragma unroll
    for (int c = 0; c < M; c++)
        thc[c] = __shfl_sync(0xFFFFFFFFu, th, src[c]);
    float a[NACC];
    a[0] = bias;
    #pragma unroll
    for (int q = 1; q < NACC; q++) a[q] = 0.f;
    #pragma unroll
    for (int c = 0; c < M; c++)
        a[c % NACC] = fmaf(w[c], thc[c], a[c % NACC]);
    float s = a[0];
    if (NACC == 2) s = a[0] + a[1];
    if (NACC == 4) s = (a[0] + a[1]) + (a[2] + a[3]);
    float nth;
    asm("tanh.approx.f32 %0, %1;" : "=f"(nth) : "f"(s));
    return nth;
}

// ---------------------------------------------------------------------------
// Chunked solver: every lane owns one v; warm-up halo from decoupled guess.
// ---------------------------------------------------------------------------
template <int M, int NACC>
__device__ __forceinline__ void chunkBody(float* __restrict__ out) {
    const int lane = threadIdx.x;
    const int v = (lane < V_VOC) ? lane : (V_VOC - 1);
    const bool writer = (lane < V_VOC);

    const float B = g_B28[v];
    float w[M];
    int src[M];
    #pragma unroll
    for (int c = 0; c < M; c++) {
        w[c]   = g_W28[v * V_VOC + c];
        src[c] = g_actV[c];
    }

    const int halo = g_halo;
    const int t0 = blockIdx.x * CHUNK;
    const int ts = (blockIdx.x == 0) ? 0 : (t0 - halo);
    const int te = t0 + CHUNK;

    float th;
    if (blockIdx.x == 0) {
        th = -1.f;                                 // y_prev = 0 exactly
    } else {
        const float s0 = B + __ldg(&g_U[(ts - 1) * V_VOC + v]);
        asm("tanh.approx.f32 %0, %1;" : "=f"(th) : "f"(s0));
    }

    float ub[8];
    #pragma unroll
    for (int i = 0; i < 8; i++) ub[i] = __ldg(&g_U[(ts + i) * V_VOC + v]);

    for (int t = ts; t < te; t += 8) {
        #pragma unroll
        for (int i = 0; i < 8; i++) {
            const float bias = B + ub[i];
            const int tn = t + i + 8;
            if (tn < te) ub[i] = __ldg(&g_U[tn * V_VOC + v]);
            th = stepFn<M, NACC>(w, src, th, bias);
            if (writer && (t + i) >= t0)
                out[(t + i) * V_VOC + v] = fmaf(0.5f, th, 0.5f);
        }
    }
}

// Full-serial fallback (block 0 only), same unified scheme
__device__ __forceinline__ void serialBody(float* __restrict__ out) {
    const int lane = threadIdx.x;
    const int v = (lane < V_VOC) ? lane : (V_VOC - 1);
    const bool writer = (lane < V_VOC);

    const float B = g_B28[v];
    float w[V_VOC];
    int src[V_VOC];
    #pragma unroll
    for (int c = 0; c < V_VOC; c++) {
        w[c]   = g_W28[v * V_VOC + c];
        src[c] = g_actV[c];
    }

    float ub[8];
    #pragma unroll
    for (int i = 0; i < 8; i++) ub[i] = g_U[i * V_VOC + v];

    float th = -1.0f;
    for (int t = 0; t < T_FRAMES; t += 8) {
        #pragma unroll
        for (int i = 0; i < 8; i++) {
            const float bias = B + ub[i];
            const int tn = t + i + 8;
            if (tn < T_FRAMES) ub[i] = __ldg(&g_U[tn * V_VOC + v]);
            th = stepFn<V_VOC, 4>(w, src, th, bias);
            if (writer) out[(t + i) * V_VOC + v] = fmaf(0.5f, th, 0.5f);
        }
    }
}

__global__ void __launch_bounds__(32) kD_solve(float* __restrict__ out) {
    if (g_useSerial) {
        if (blockIdx.x != 0) return;
        serialBody(out);
        return;
    }
    const int m = g_m;
    if      (m <= 4) chunkBody<4, 2>(out);
    else if (m <= 8) chunkBody<8, 4>(out);
    else             chunkBody<16, 4>(out);
}

// ---------------------------------------------------------------------------
extern "C" void kernel_launch(void* const* d_in, const int* in_sizes, int n_in,
                              void* d_out, int out_size) {
    const float* x  = (const float*)d_in[0];   // (1, 2048, 1024)
    // d_in[1..3] = Wa, Ua, Va : mathematically dead (softmax over size-1 axis)
    const float* Wo = (const float*)d_in[4];   // (28, 28)
    const float* Uo = (const float*)d_in[5];   // (28, 1024)
    const float* Co = (const float*)d_in[6];   // (28, 1024)
    float* out = (float*)d_out;                // (1, 2048, 28)

    void* coPtr = nullptr;
    cudaGetSymbolAddress(&coPtr, g_CO);
    cudaMemsetAsync(coPtr, 0, V_VOC * sizeof(float));

    kA_computeU<<<NBLK_A, 128>>>(x, Uo, Co);
    kMeta<<<1, 896>>>(Wo);
    kD_solve<<<NCHUNK, 32>>>(out);
}

// round 11
// speedup vs baseline: 1.9602x; 1.9602x over previous
#include <cuda_runtime.h>

#define T_FRAMES 2048
#define D_HID    1024
#define V_VOC    28
#define ROWS     8
#define NBLK_A   (T_FRAMES / ROWS)      // 256
#define NPART    (NBLK_A * 4)           // 1024 partials per v (4 row-pairs/block)
#define CHUNK    16
#define NCHUNK   (T_FRAMES / CHUNK)     // 128

// ---------------------------------------------------------------------------
// Device scratch
// ---------------------------------------------------------------------------
__device__ float g_U[T_FRAMES * V_VOC];   // 0.5*(Uo . x[t-1]); row 0 rewritten by kMeta
__device__ float g_S[D_HID];              // colsum of x (atomics; memset to 0)
__device__ float g_CO[V_VOC];             // 0.5*(Co @ S)
__device__ float g_partMn[V_VOC * NPART];
__device__ float g_partMx[V_VOC * NPART];
__device__ int   g_m;                     // number of active outputs
__device__ int   g_useSerial;
__device__ int   g_halo;                  // 8 or 16
__device__ int   g_actV[32];              // rank -> active v (zero padded)
__device__ float g_B28[32];               // per-v folded bias
__device__ float g_W28[32 * V_VOC];       // per-v 0.25*Wo[v, act[j]] (zero padded)

// ---------------------------------------------------------------------------
// Kernel A: g_U[t+1][v] = 0.5*(Uo[v] . x[t]).
// 8 t-rows/block, 16 warps: warp w -> v-group (w&3, 7 v) x row-pair (w>>2).
// Weight traffic amortized over 8 rows/block; ~28 warps/SM in flight.
// Fused colsum via spread atomics.
// ---------------------------------------------------------------------------
__global__ void __launch_bounds__(512) kA_computeU(const float* __restrict__ x,
                                                   const float* __restrict__ Uo) {
    __shared__ float xs[ROWS][D_HID];              // 32 KB
    const int t0 = blockIdx.x * ROWS;

    const float4* xv = reinterpret_cast<const float4*>(x + (size_t)t0 * D_HID);
    float4* sv = reinterpret_cast<float4*>(&xs[0][0]);
    #pragma unroll
    for (int i = 0; i < ROWS * D_HID / 4 / 512; i++)
        sv[threadIdx.x + 512 * i] = xv[threadIdx.x + 512 * i];
    __syncthreads();

    const int warp = threadIdx.x >> 5;
    const int lane = threadIdx.x & 31;
    const int vg = warp & 3;                       // v-group: 7 v
    const int rp = warp >> 2;                      // row-pair: rows 2rp, 2rp+1
    const int r0 = rp * 2;

    // fused colsum (two d per thread, distinct addresses)
    #pragma unroll
    for (int i = 0; i < 2; i++) {
        const int d = threadIdx.x + 512 * i;
        float s = 0.f;
        #pragma unroll
        for (int r = 0; r < ROWS; r++) s += xs[r][d];
        atomicAdd(&g_S[d], s);
    }

    float acc0[7], acc1[7];
    #pragma unroll
    for (int vi = 0; vi < 7; vi++) { acc0[vi] = 0.f; acc1[vi] = 0.f; }

    #pragma unroll
    for (int j = 0; j < 8; j++) {
        const int dd = j * 128 + lane * 4;
        const float4 xr0 = *reinterpret_cast<const float4*>(&xs[r0][dd]);
        const float4 xr1 = *reinterpret_cast<const float4*>(&xs[r0 + 1][dd]);
        #pragma unroll
        for (int vi = 0; vi < 7; vi++) {
            const int v = vg * 7 + vi;
            const float4 u4 = __ldg(reinterpret_cast<const float4*>(&Uo[v * D_HID + dd]));
            float a = fmaf(u4.x, xr0.x, acc0[vi]);
            a = fmaf(u4.y, xr0.y, a);
            a = fmaf(u4.z, xr0.z, a);
            acc0[vi] = fmaf(u4.w, xr0.w, a);
            float b = fmaf(u4.x, xr1.x, acc1[vi]);
            b = fmaf(u4.y, xr1.y, b);
            b = fmaf(u4.z, xr1.z, b);
            acc1[vi] = fmaf(u4.w, xr1.w, b);
        }
    }

    #pragma unroll
    for (int vi = 0; vi < 7; vi++) {
        const int v = vg * 7 + vi;
        float s0 = acc0[vi], s1 = acc1[vi];
        #pragma unroll
        for (int o = 16; o; o >>= 1) {
            s0 += __shfl_xor_sync(0xFFFFFFFFu, s0, o);
            s1 += __shfl_xor_sync(0xFFFFFFFFu, s1, o);
        }
        if (lane == 0) {
            const float uh0 = 0.5f * s0;           // -> t0+r0+1  (<= 2047)
            g_U[(t0 + r0 + 1) * V_VOC + v] = uh0;
            float mn = uh0, mx = uh0;
            const int t2 = t0 + r0 + 2;
            if (t2 < T_FRAMES) {
                const float uh1 = 0.5f * s1;
                g_U[t2 * V_VOC + v] = uh1;
                mn = fminf(mn, uh1);
                mx = fmaxf(mx, uh1);
            }
            g_partMn[v * NPART + blockIdx.x * 4 + rp] = mn;
            g_partMx[v * NPART + blockIdx.x * 4 + rp] = mx;
        }
    }
}

// ---------------------------------------------------------------------------
// Kernel Meta: CO + min/max reduce + classify + unified tables. 28 warps.
// ---------------------------------------------------------------------------
__global__ void __launch_bounds__(896) kMeta(const float* __restrict__ Co,
                                             const float* __restrict__ Wo) {
    const int warp = threadIdx.x >> 5;   // == v
    const int lane = threadIdx.x & 31;

    {   // CO[v] = 0.5 * (Co[v] . S)
        float s = 0.f;
        #pragma unroll 8
        for (int j = 0; j < 32; j++) {
            const int d = j * 32 + lane;
            s = fmaf(__ldg(&Co[warp * D_HID + d]), g_S[d], s);
        }
        #pragma unroll
        for (int o = 16; o; o >>= 1) s += __shfl_xor_sync(0xFFFFFFFFu, s, o);
        if (lane == 0) g_CO[warp] = 0.5f * s;
    }
    {   // per-v min/max reduce over NPART partials (include t=0 value 0)
        float mn = 0.f, mx = 0.f;
        #pragma unroll
        for (int i = 0; i < NPART / 32; i++) {
            mn = fminf(mn, g_partMn[warp * NPART + lane + 32 * i]);
            mx = fmaxf(mx, g_partMx[warp * NPART + lane + 32 * i]);
        }
        #pragma unroll
        for (int o = 16; o; o >>= 1) {
            mn = fminf(mn, __shfl_xor_sync(0xFFFFFFFFu, mn, o));
            mx = fmaxf(mx, __shfl_xor_sync(0xFFFFFFFFu, mx, o));
        }
        if (lane == 0) { g_partMn[warp * NPART] = mn; g_partMx[warp * NPART] = mx; }
    }
    __syncthreads();
    if (warp != 0) return;

    // warp 0: classification + tables. All shuffles uniform.
    const bool valid = lane < V_VOC;
    const int vIdx = valid ? lane : 0;

    float w[V_VOC];
    float rowNeg = 0.f, rowPos = 0.f;
    #pragma unroll
    for (int k = 0; k < V_VOC; k++) {
        w[k] = Wo[vIdx * V_VOC + k];
        rowNeg += fminf(w[k], 0.f);
        rowPos += fmaxf(w[k], 0.f);
    }
    const float coh  = g_CO[vIdx];
    const float sMin = coh + g_partMn[vIdx * NPART] + 0.5f * rowNeg;
    const float sMax = coh + g_partMx[vIdx * NPART] + 0.5f * rowPos;

    int cls = 2;
    if (sMin > 7.f)  cls = 1;
    if (sMax < -7.f) cls = 0;
    if (!valid)      cls = 0;

    const unsigned amask = __ballot_sync(0xFFFFFFFFu, cls == 2) & 0x0FFFFFFFu;
    const int m = __popc(amask);
    if (lane == 0) g_m = m;

    int clsA[V_VOC];
    #pragma unroll
    for (int k = 0; k < V_VOC; k++)
        clsA[k] = __shfl_sync(0xFFFFFFFFu, cls, k);

    float s1 = 0.f;
    #pragma unroll
    for (int k = 0; k < V_VOC; k++)
        if (clsA[k] == 1) s1 += w[k];

    int act[V_VOC];
    int cnt = 0;
    #pragma unroll
    for (int k = 0; k < V_VOC; k++)
        if ((amask >> k) & 1u) act[cnt++] = k;

    // unified per-v tables: same folded form for active AND saturated rows
    float sa = 0.f, qrow = 0.f;
    #pragma unroll
    for (int j = 0; j < V_VOC; j++) {
        float wj = 0.f;
        if (j < m) wj = w[act[j]];
        g_W28[lane * V_VOC + j] = 0.25f * wj;
        sa += wj;
        qrow += 0.25f * fabsf(wj);
    }
    g_B28[lane] = coh + 0.5f * s1 + 0.25f * sa;
    g_actV[lane] = (lane < m) ? act[lane] : 0;

    if (cls != 2) qrow = 0.f;          // contraction over the active subsystem only
    #pragma unroll
    for (int o = 16; o; o >>= 1)
        qrow = fmaxf(qrow, __shfl_xor_sync(0xFFFFFFFFu, qrow, o));
    if (lane == 0) {
        g_useSerial = (m > 16 || qrow > 0.40f) ? 1 : 0;
        const float q = fmaxf(qrow, 1e-4f);
        g_halo = (9.f * __logf(q) < -16.2f) ? 8 : 16;
    }

    // t=0 exactness under folded-bias form: Uh0 = -0.5*s1
    if (valid) g_U[lane] = -0.5f * s1;
}

// ---------------------------------------------------------------------------
// One unified recurrence step (indexed shuffles from the active lanes)
// ---------------------------------------------------------------------------
template <int M, int NACC>
__device__ __forceinline__ float stepFn(const float* __restrict__ w,
                                        const int* __restrict__ src,
                                        float th, float bias) {
    float thc[M];
    #pragma unroll
    for (int c = 0; c < M; c++)
        thc[c] = __shfl_sync(0xFFFFFFFFu, th, src[c]);
    float a[NACC];
    a[0] = bias;
    #pragma unroll
    for (int q = 1; q < NACC; q++) a[q] = 0.f;
    #pragma unroll
    for (int c = 0; c < M; c++)
        a[c % NACC] = fmaf(w[c], thc[c], a[c % NACC]);
    float s = a[0];
    if (NACC == 2) s = a[0] + a[1];
    if (NACC == 4) s = (a[0] + a[1]) + (a[2] + a[3]);
    float nth;
    asm("tanh.approx.f32 %0, %1;" : "=f"(nth) : "f"(s));
    return nth;
}

// ---------------------------------------------------------------------------
// Chunked solver: every lane owns one v; warm-up halo from decoupled guess.
// ---------------------------------------------------------------------------
template <int M, int NACC>
__device__ __forceinline__ void chunkBody(float* __restrict__ out) {
    const int lane = threadIdx.x;
    const int v = (lane < V_VOC) ? lane : (V_VOC - 1);
    const bool writer = (lane < V_VOC);

    const float B = g_B28[v];
    float w[M];
    int src[M];
    #pragma unroll
    for (int c = 0; c < M; c++) {
        w[c]   = g_W28[v * V_VOC + c];
        src[c] = g_actV[c];
    }

    const int halo = g_halo;
    const int t0 = blockIdx.x * CHUNK;
    const int ts = (blockIdx.x == 0) ? 0 : (t0 - halo);
    const int te = t0 + CHUNK;

    float th;
    if (blockIdx.x == 0) {
        th = -1.f;                                 // y_prev = 0 exactly
    } else {
        const float s0 = B + __ldg(&g_U[(ts - 1) * V_VOC + v]);
        asm("tanh.approx.f32 %0, %1;" : "=f"(th) : "f"(s0));
    }

    float ub[8];
    #pragma unroll
    for (int i = 0; i < 8; i++) ub[i] = __ldg(&g_U[(ts + i) * V_VOC + v]);

    for (int t = ts; t < te; t += 8) {
        #pragma unroll
        for (int i = 0; i < 8; i++) {
            const float bias = B + ub[i];
            const int tn = t + i + 8;
            if (tn < te) ub[i] = __ldg(&g_U[tn * V_VOC + v]);
            th = stepFn<M, NACC>(w, src, th, bias);
            if (writer && (t + i) >= t0)
                out[(t + i) * V_VOC + v] = fmaf(0.5f, th, 0.5f);
        }
    }
}

// Full-serial fallback (block 0 only), same unified scheme
__device__ __forceinline__ void serialBody(float* __restrict__ out) {
    const int lane = threadIdx.x;
    const int v = (lane < V_VOC) ? lane : (V_VOC - 1);
    const bool writer = (lane < V_VOC);

    const float B = g_B28[v];
    float w[V_VOC];
    int src[V_VOC];
    #pragma unroll
    for (int c = 0; c < V_VOC; c++) {
        w[c]   = g_W28[v * V_VOC + c];
        src[c] = g_actV[c];
    }

    float ub[8];
    #pragma unroll
    for (int i = 0; i < 8; i++) ub[i] = g_U[i * V_VOC + v];

    float th = -1.0f;
    for (int t = 0; t < T_FRAMES; t += 8) {
        #pragma unroll
        for (int i = 0; i < 8; i++) {
            const float bias = B + ub[i];
            const int tn = t + i + 8;
            if (tn < T_FRAMES) ub[i] = __ldg(&g_U[tn * V_VOC + v]);
            th = stepFn<V_VOC, 4>(w, src, th, bias);
            if (writer) out[(t + i) * V_VOC + v] = fmaf(0.5f, th, 0.5f);
        }
    }
}

__global__ void __launch_bounds__(32) kD_solve(float* __restrict__ out) {
    if (g_useSerial) {
        if (blockIdx.x != 0) return;
        serialBody(out);
        return;
    }
    const int m = g_m;
    if      (m <= 4) chunkBody<4, 2>(out);
    else if (m <= 8) chunkBody<8, 4>(out);
    else             chunkBody<16, 4>(out);
}

// ---------------------------------------------------------------------------
extern "C" void kernel_launch(void* const* d_in, const int* in_sizes, int n_in,
                              void* d_out, int out_size) {
    const float* x  = (const float*)d_in[0];   // (1, 2048, 1024)
    // d_in[1..3] = Wa, Ua, Va : mathematically dead (softmax over size-1 axis)
    const float* Wo = (const float*)d_in[4];   // (28, 28)
    const float* Uo = (const float*)d_in[5];   // (28, 1024)
    const float* Co = (const float*)d_in[6];   // (28, 1024)
    float* out = (float*)d_out;                // (1, 2048, 28)

    void* sPtr = nullptr;
    cudaGetSymbolAddress(&sPtr, g_S);
    cudaMemsetAsync(sPtr, 0, D_HID * sizeof(float));

    kA_computeU<<<NBLK_A, 512>>>(x, Uo);
    kMeta<<<1, 896>>>(Co, Wo);
    kD_solve<<<NCHUNK, 32>>>(out);
}

// round 12
// speedup vs baseline: 1.9973x; 1.0189x over previous
#include <cuda_runtime.h>

#define T_FRAMES 2048
#define D_HID    1024
#define V_VOC    28
#define ROWS     8
#define NBLK_A   (T_FRAMES / ROWS)      // 256
#define NPART    (NBLK_A * 2)           // 512 partials per v (2 row-halves/block)
#define CHUNK    16
#define NCHUNK   (T_FRAMES / CHUNK)     // 128

// ---------------------------------------------------------------------------
// Device scratch
// ---------------------------------------------------------------------------
__device__ float g_U[T_FRAMES * V_VOC];   // 0.5*(Uo . x[t-1]); row 0 rewritten by kMeta
__device__ float g_S[D_HID];              // colsum of x (atomics; memset to 0)
__device__ float g_CO[V_VOC];             // 0.5*(Co @ S)
__device__ float g_partMn[V_VOC * NPART];
__device__ float g_partMx[V_VOC * NPART];
__device__ int   g_m;                     // number of active outputs
__device__ int   g_useSerial;
__device__ int   g_halo;                  // 8 or 16
__device__ int   g_actV[32];              // rank -> active v (zero padded)
__device__ float g_B28[32];               // per-v folded bias
__device__ float g_W28[32 * V_VOC];       // per-v 0.25*Wo[v, act[j]] (zero padded)

// ---------------------------------------------------------------------------
// Kernel A: g_U[t+1][v] = 0.5*(Uo[v] . x[t]).
// 8 t-rows/block, 256 threads (8 warps): warp w -> v-group (w&3, 7 v) x
// row-half (w>>2, 4 rows). Per-j: ALL 7 Uo float4 loads batched into regs
// BEFORE the 112-FMA block (explicit MLP=7); 2 blocks/SM, grid fits 1 wave.
// Fused colsum via spread atomics.
// ---------------------------------------------------------------------------
__global__ void __launch_bounds__(256) kA_computeU(const float* __restrict__ x,
                                                   const float* __restrict__ Uo) {
    __shared__ float xs[ROWS][D_HID];              // 32 KB
    const int t0 = blockIdx.x * ROWS;

    const float4* xv = reinterpret_cast<const float4*>(x + (size_t)t0 * D_HID);
    float4* sv = reinterpret_cast<float4*>(&xs[0][0]);
    #pragma unroll
    for (int i = 0; i < ROWS * D_HID / 4 / 256; i++)
        sv[threadIdx.x + 256 * i] = xv[threadIdx.x + 256 * i];
    __syncthreads();

    const int warp = threadIdx.x >> 5;
    const int lane = threadIdx.x & 31;
    const int vg = warp & 3;                       // v-group: 7 v
    const int rh = warp >> 2;                      // row-half: 4 rows
    const int r0 = rh * 4;

    // fused colsum (four d per thread, distinct addresses)
    #pragma unroll
    for (int i = 0; i < 4; i++) {
        const int d = threadIdx.x + 256 * i;
        float s = 0.f;
        #pragma unroll
        for (int r = 0; r < ROWS; r++) s += xs[r][d];
        atomicAdd(&g_S[d], s);
    }

    float acc[7][4];
    #pragma unroll
    for (int vi = 0; vi < 7; vi++)
        #pragma unroll
        for (int r = 0; r < 4; r++) acc[vi][r] = 0.f;

    #pragma unroll
    for (int j = 0; j < 8; j++) {
        const int dd = j * 128 + lane * 4;

        // batch ALL weight loads for this j first (7 independent LDG.128)
        float4 ub[7];
        #pragma unroll
        for (int vi = 0; vi < 7; vi++)
            ub[vi] = __ldg(reinterpret_cast<const float4*>(&Uo[(vg * 7 + vi) * D_HID + dd]));

        float4 xr[4];
        #pragma unroll
        for (int r = 0; r < 4; r++)
            xr[r] = *reinterpret_cast<const float4*>(&xs[r0 + r][dd]);

        #pragma unroll
        for (int vi = 0; vi < 7; vi++) {
            #pragma unroll
            for (int r = 0; r < 4; r++) {
                float a = fmaf(ub[vi].x, xr[r].x, acc[vi][r]);
                a = fmaf(ub[vi].y, xr[r].y, a);
                a = fmaf(ub[vi].z, xr[r].z, a);
                acc[vi][r] = fmaf(ub[vi].w, xr[r].w, a);
            }
        }
    }

    #pragma unroll
    for (int vi = 0; vi < 7; vi++) {
        const int v = vg * 7 + vi;
        float mn = 1e30f, mx = -1e30f;
        #pragma unroll
        for (int r = 0; r < 4; r++) {
            float s = acc[vi][r];
            #pragma unroll
            for (int o = 16; o; o >>= 1) s += __shfl_xor_sync(0xFFFFFFFFu, s, o);
            const int t = t0 + r0 + r + 1;
            if (lane == 0 && t < T_FRAMES) {
                const float uh = 0.5f * s;
                g_U[t * V_VOC + v] = uh;
                mn = fminf(mn, uh);
                mx = fmaxf(mx, uh);
            }
        }
        if (lane == 0) {
            g_partMn[v * NPART + blockIdx.x * 2 + rh] = mn;
            g_partMx[v * NPART + blockIdx.x * 2 + rh] = mx;
        }
    }
}

// ---------------------------------------------------------------------------
// Kernel Meta: CO + min/max reduce + classify + unified tables. 28 warps.
// ---------------------------------------------------------------------------
__global__ void __launch_bounds__(896) kMeta(const float* __restrict__ Co,
                                             const float* __restrict__ Wo) {
    const int warp = threadIdx.x >> 5;   // == v
    const int lane = threadIdx.x & 31;

    {   // CO[v] = 0.5 * (Co[v] . S)
        float s = 0.f;
        #pragma unroll 8
        for (int j = 0; j < 32; j++) {
            const int d = j * 32 + lane;
            s = fmaf(__ldg(&Co[warp * D_HID + d]), g_S[d], s);
        }
        #pragma unroll
        for (int o = 16; o; o >>= 1) s += __shfl_xor_sync(0xFFFFFFFFu, s, o);
        if (lane == 0) g_CO[warp] = 0.5f * s;
    }
    {   // per-v min/max reduce over NPART partials (include t=0 value 0)
        float mn = 0.f, mx = 0.f;
        #pragma unroll
        for (int i = 0; i < NPART / 32; i++) {
            mn = fminf(mn, g_partMn[warp * NPART + lane + 32 * i]);
            mx = fmaxf(mx, g_partMx[warp * NPART + lane + 32 * i]);
        }
        #pragma unroll
        for (int o = 16; o; o >>= 1) {
            mn = fminf(mn, __shfl_xor_sync(0xFFFFFFFFu, mn, o));
            mx = fmaxf(mx, __shfl_xor_sync(0xFFFFFFFFu, mx, o));
        }
        if (lane == 0) { g_partMn[warp * NPART] = mn; g_partMx[warp * NPART] = mx; }
    }
    __syncthreads();
    if (warp != 0) return;

    // warp 0: classification + tables. All shuffles uniform.
    const bool valid = lane < V_VOC;
    const int vIdx = valid ? lane : 0;

    float w[V_VOC];
    float rowNeg = 0.f, rowPos = 0.f;
    #pragma unroll
    for (int k = 0; k < V_VOC; k++) {
        w[k] = Wo[vIdx * V_VOC + k];
        rowNeg += fminf(w[k], 0.f);
        rowPos += fmaxf(w[k], 0.f);
    }
    const float coh  = g_CO[vIdx];
    const float sMin = coh + g_partMn[vIdx * NPART] + 0.5f * rowNeg;
    const float sMax = coh + g_partMx[vIdx * NPART] + 0.5f * rowPos;

    int cls = 2;
    if (sMin > 7.f)  cls = 1;
    if (sMax < -7.f) cls = 0;
    if (!valid)      cls = 0;

    const unsigned amask = __ballot_sync(0xFFFFFFFFu, cls == 2) & 0x0FFFFFFFu;
    const int m = __popc(amask);
    if (lane == 0) g_m = m;

    int clsA[V_VOC];
    #pragma unroll
    for (int k = 0; k < V_VOC; k++)
        clsA[k] = __shfl_sync(0xFFFFFFFFu, cls, k);

    float s1 = 0.f;
    #pragma unroll
    for (int k = 0; k < V_VOC; k++)
        if (clsA[k] == 1) s1 += w[k];

    int act[V_VOC];
    int cnt = 0;
    #pragma unroll
    for (int k = 0; k < V_VOC; k++)
        if ((amask >> k) & 1u) act[cnt++] = k;

    // unified per-v tables: same folded form for active AND saturated rows
    float sa = 0.f, qrow = 0.f;
    #pragma unroll
    for (int j = 0; j < V_VOC; j++) {
        float wj = 0.f;
        if (j < m) wj = w[act[j]];
        g_W28[lane * V_VOC + j] = 0.25f * wj;
        sa += wj;
        qrow += 0.25f * fabsf(wj);
    }
    g_B28[lane] = coh + 0.5f * s1 + 0.25f * sa;
    g_actV[lane] = (lane < m) ? act[lane] : 0;

    if (cls != 2) qrow = 0.f;          // contraction over the active subsystem only
    #pragma unroll
    for (int o = 16; o; o >>= 1)
        qrow = fmaxf(qrow, __shfl_xor_sync(0xFFFFFFFFu, qrow, o));
    if (lane == 0) {
        g_useSerial = (m > 16 || qrow > 0.40f) ? 1 : 0;
        const float q = fmaxf(qrow, 1e-4f);
        g_halo = (9.f * __logf(q) < -16.2f) ? 8 : 16;
    }

    // t=0 exactness under folded-bias form: Uh0 = -0.5*s1
    if (valid) g_U[lane] = -0.5f * s1;
}

// ---------------------------------------------------------------------------
// One unified recurrence step (indexed shuffles from the active lanes)
// ---------------------------------------------------------------------------
template <int M, int NACC>
__device__ __forceinline__ float stepFn(const float* __restrict__ w,
                                        const int* __restrict__ src,
                                        float th, float bias) {
    float thc[M];
    #pragma unroll
    for (int c = 0; c < M; c++)
        thc[c] = __shfl_sync(0xFFFFFFFFu, th, src[c]);
    float a[NACC];
    a[0] = bias;
    #pragma unroll
    for (int q = 1; q < NACC; q++) a[q] = 0.f;
    #pragma unroll
    for (int c = 0; c < M; c++)
        a[c % NACC] = fmaf(w[c], thc[c], a[c % NACC]);
    float s = a[0];
    if (NACC == 2) s = a[0] + a[1];
    if (NACC == 4) s = (a[0] + a[1]) + (a[2] + a[3]);
    float nth;
    asm("tanh.approx.f32 %0, %1;" : "=f"(nth) : "f"(s));
    return nth;
}

// ---------------------------------------------------------------------------
// Chunked solver: every lane owns one v; warm-up halo from decoupled guess.
// ---------------------------------------------------------------------------
template <int M, int NACC>
__device__ __forceinline__ void chunkBody(float* __restrict__ out) {
    const int lane = threadIdx.x;
    const int v = (lane < V_VOC) ? lane : (V_VOC - 1);
    const bool writer = (lane < V_VOC);

    const float B = g_B28[v];
    float w[M];
    int src[M];
    #pragma unroll
    for (int c = 0; c < M; c++) {
        w[c]   = g_W28[v * V_VOC + c];
        src[c] = g_actV[c];
    }

    const int halo = g_halo;
    const int t0 = blockIdx.x * CHUNK;
    const int ts = (blockIdx.x == 0) ? 0 : (t0 - halo);
    const int te = t0 + CHUNK;

    float th;
    if (blockIdx.x == 0) {
        th = -1.f;                                 // y_prev = 0 exactly
    } else {
        const float s0 = B + __ldg(&g_U[(ts - 1) * V_VOC + v]);
        asm("tanh.approx.f32 %0, %1;" : "=f"(th) : "f"(s0));
    }

    float ub[8];
    #pragma unroll
    for (int i = 0; i < 8; i++) ub[i] = __ldg(&g_U[(ts + i) * V_VOC + v]);

    for (int t = ts; t < te; t += 8) {
        #pragma unroll
        for (int i = 0; i < 8; i++) {
            const float bias = B + ub[i];
            const int tn = t + i + 8;
            if (tn < te) ub[i] = __ldg(&g_U[tn * V_VOC + v]);
            th = stepFn<M, NACC>(w, src, th, bias);
            if (writer && (t + i) >= t0)
                out[(t + i) * V_VOC + v] = fmaf(0.5f, th, 0.5f);
        }
    }
}

// Full-serial fallback (block 0 only), same unified scheme
__device__ __forceinline__ void serialBody(float* __restrict__ out) {
    const int lane = threadIdx.x;
    const int v = (lane < V_VOC) ? lane : (V_VOC - 1);
    const bool writer = (lane < V_VOC);

    const float B = g_B28[v];
    float w[V_VOC];
    int src[V_VOC];
    #pragma unroll
    for (int c = 0; c < V_VOC; c++) {
        w[c]   = g_W28[v * V_VOC + c];
        src[c] = g_actV[c];
    }

    float ub[8];
    #pragma unroll
    for (int i = 0; i < 8; i++) ub[i] = g_U[i * V_VOC + v];

    float th = -1.0f;
    for (int t = 0; t < T_FRAMES; t += 8) {
        #pragma unroll
        for (int i = 0; i < 8; i++) {
            const float bias = B + ub[i];
            const int tn = t + i + 8;
            if (tn < T_FRAMES) ub[i] = __ldg(&g_U[tn * V_VOC + v]);
            th = stepFn<V_VOC, 4>(w, src, th, bias);
            if (writer) out[(t + i) * V_VOC + v] = fmaf(0.5f, th, 0.5f);
        }
    }
}

__global__ void __launch_bounds__(32) kD_solve(float* __restrict__ out) {
    if (g_useSerial) {
        if (blockIdx.x != 0) return;
        serialBody(out);
        return;
    }
    const int m = g_m;
    if      (m <= 4) chunkBody<4, 2>(out);
    else if (m <= 8) chunkBody<8, 4>(out);
    else             chunkBody<16, 4>(out);
}

// ---------------------------------------------------------------------------
extern "C" void kernel_launch(void* const* d_in, const int* in_sizes, int n_in,
                              void* d_out, int out_size) {
    const float* x  = (const float*)d_in[0];   // (1, 2048, 1024)
    // d_in[1..3] = Wa, Ua, Va : mathematically dead (softmax over size-1 axis)
    const float* Wo = (const float*)d_in[4];   // (28, 28)
    const float* Uo = (const float*)d_in[5];   // (28, 1024)
    const float* Co = (const float*)d_in[6];   // (28, 1024)
    float* out = (float*)d_out;                // (1, 2048, 28)

    void* sPtr = nullptr;
    cudaGetSymbolAddress(&sPtr, g_S);
    cudaMemsetAsync(sPtr, 0, D_HID * sizeof(float));

    kA_computeU<<<NBLK_A, 256>>>(x, Uo);
    kMeta<<<1, 896>>>(Co, Wo);
    kD_solve<<<NCHUNK, 32>>>(out);
}